// round 15
// baseline (speedup 1.0000x reference)
#include <cuda_runtime.h>
#include <cstdint>
#include <cstddef>

#define SCALE 0.17677669529663687f            // 32^-0.5
#define S2LOG (SCALE * 1.4426950408889634f)   // SCALE * log2(e)

// ---------------- scratch (allocation-free rule) ----------------
static __device__ float g_qkT [(size_t)8 * 1024 * 512];     // q,k transposed [b][n][512] (tf32)
static __device__ float g_v   [(size_t)8 * 256 * 1024];     // v [b][c][n] (tf32)
static __device__ float g_attT[(size_t)8 * 1024 * 256];     // final attn+lepe [b][n][c] (tf32)
static __device__ float g_part[(size_t)2 * 8 * 1024 * 256]; // split-K partial O
static __device__ float g_rs  [(size_t)2 * 64 * 1024];      // split-K partial row sums

// ---------------- helpers ----------------
__device__ __forceinline__ uint32_t f2tf(float x) {
    uint32_t r; asm("cvt.rna.tf32.f32 %0, %1;" : "=r"(r) : "f"(x)); return r;
}
__device__ __forceinline__ float tf(float x) { return __uint_as_float(f2tf(x)); }

__device__ __forceinline__ void mma8(float* d, const uint32_t* a, const uint32_t* b) {
    asm volatile(
        "mma.sync.aligned.m16n8k8.row.col.f32.tf32.tf32.f32 "
        "{%0,%1,%2,%3}, {%4,%5,%6,%7}, {%8,%9}, {%0,%1,%2,%3};"
        : "+f"(d[0]), "+f"(d[1]), "+f"(d[2]), "+f"(d[3])
        : "r"(a[0]), "r"(a[1]), "r"(a[2]), "r"(a[3]), "r"(b[0]), "r"(b[1]));
}

// ---------------------------------------------------------------------------
// QKV GEMM (137.6-winner, verbatim): qkv[m][n] = sum_k W[m][k]*x[b][k][n]
// ---------------------------------------------------------------------------
__global__ __launch_bounds__(128) void gemm_qkv(const float* __restrict__ W,
                                                const float* __restrict__ X)
{
    __shared__ float sm[4608];
    float* As = sm;          // 64 x 36  [m][k]
    float* Bs = sm + 2304;   // 32 x 72  [k][n]

    const int tid = threadIdx.x;
    const int bm = blockIdx.y * 64, bn = blockIdx.x * 64, b = blockIdx.z;
    const float* Xb = X + (size_t)b * 256 * 1024;

    const int lane = tid & 31, wrp = tid >> 5;
    const int g = lane >> 2, t = lane & 3;
    const int qb = wrp * 16;

    float cf[8][4] = {};

    for (int kc = 0; kc < 8; ++kc) {
        const int k0 = kc * 32;
        if (kc) __syncthreads();
        #pragma unroll
        for (int i = 0; i < 4; ++i) {
            const int m = (tid >> 3) + i * 16;
            const int kq = (tid & 7) * 4;
            float4 av = *(const float4*)&W[(size_t)(bm + m) * 256 + k0 + kq];
            av.x = tf(av.x); av.y = tf(av.y); av.z = tf(av.z); av.w = tf(av.w);
            *(float4*)&As[m * 36 + kq] = av;
            const int k = (tid >> 4) + i * 8;
            const int n4 = (tid & 15) * 4;
            float4 bv = *(const float4*)&Xb[(size_t)(k0 + k) * 1024 + bn + n4];
            bv.x = tf(bv.x); bv.y = tf(bv.y); bv.z = tf(bv.z); bv.w = tf(bv.w);
            *(float4*)&Bs[k * 72 + n4] = bv;
        }
        __syncthreads();

        #pragma unroll
        for (int kk = 0; kk < 4; ++kk) {
            const int r1 = (qb + g) * 36 + kk * 8 + t;
            const int r2 = r1 + 8 * 36;
            uint32_t a[4];
            a[0] = __float_as_uint(As[r1]);     a[1] = __float_as_uint(As[r2]);
            a[2] = __float_as_uint(As[r1 + 4]); a[3] = __float_as_uint(As[r2 + 4]);
            #pragma unroll
            for (int nt = 0; nt < 8; ++nt) {
                uint32_t bb[2];
                bb[0] = __float_as_uint(Bs[(kk * 8 + t) * 72 + nt * 8 + g]);
                bb[1] = __float_as_uint(Bs[(kk * 8 + t + 4) * 72 + nt * 8 + g]);
                mma8(cf[nt], a, bb);
            }
        }
    }
    __syncthreads();

    if (bm < 512) {
        float* CsT = sm;    // 64 x 68, [n][m]
        #pragma unroll
        for (int nt = 0; nt < 8; ++nt) {
            const int n0 = nt * 8 + 2 * t;
            CsT[(n0 + 0) * 68 + qb + g]     = tf(cf[nt][0]);
            CsT[(n0 + 1) * 68 + qb + g]     = tf(cf[nt][1]);
            CsT[(n0 + 0) * 68 + qb + g + 8] = tf(cf[nt][2]);
            CsT[(n0 + 1) * 68 + qb + g + 8] = tf(cf[nt][3]);
        }
        __syncthreads();
        #pragma unroll
        for (int i = 0; i < 8; ++i) {
            const int flat = i * 128 + tid;
            const int n = flat >> 4, m4 = (flat & 15) * 4;
            *(float4*)&g_qkT[((size_t)b * 1024 + bn + n) * 512 + bm + m4] =
                *(const float4*)&CsT[n * 68 + m4];
        }
    } else {
        float* Cs = sm;     // 64 x 68
        const int row1 = qb + g, row2 = row1 + 8;
        #pragma unroll
        for (int nt = 0; nt < 8; ++nt) {
            *(float2*)&Cs[row1 * 68 + nt * 8 + 2 * t] = make_float2(tf(cf[nt][0]), tf(cf[nt][1]));
            *(float2*)&Cs[row2 * 68 + nt * 8 + 2 * t] = make_float2(tf(cf[nt][2]), tf(cf[nt][3]));
        }
        __syncthreads();
        #pragma unroll
        for (int i = 0; i < 8; ++i) {
            const int flat = i * 128 + tid;
            const int m = flat >> 4, n4 = (flat & 15) * 4;
            *(float4*)&g_v[((size_t)b * 256 + bm - 512 + m) * 1024 + bn + n4] =
                *(const float4*)&Cs[m * 68 + n4];
        }
    }
}

// ---------------------------------------------------------------------------
// Attention, split-K x2 (r11 kernel, verbatim): P in registers via intra-quad
// shuffles; unnormalized partials + row sums out. 1024 blocks, 5 CTA/SM.
// ---------------------------------------------------------------------------
__global__ __launch_bounds__(128, 5) void attn_kernel()
{
    __shared__ float Ks[64 * 36];
    __shared__ float Vs[32 * 68];
    __shared__ float Qs[128 * 36];

    const int tid = threadIdx.x;
    const int bx = blockIdx.x;
    const int ks = bx & 1;
    const int q0 = (bx >> 1) * 128;
    const int bh = blockIdx.y;
    const int b = bh >> 3, h = bh & 7;

    const float* qkTb = g_qkT + (size_t)b * 1024 * 512;
    const float* vp   = g_v   + ((size_t)b * 256 + h * 32) * 1024;

    const int lane = tid & 31, wrp = tid >> 5;
    const int g = lane >> 2, t = lane & 3;
    const int qb = wrp * 32;

    #pragma unroll
    for (int i = 0; i < 8; ++i) {
        const int q = (tid >> 3) + i * 16;
        const int d4 = (tid & 7) * 4;
        float4 v = *(const float4*)&qkTb[(size_t)(q0 + q) * 512 + h * 32 + d4];
        v.x = tf(v.x * S2LOG); v.y = tf(v.y * S2LOG);
        v.z = tf(v.z * S2LOG); v.w = tf(v.w * S2LOG);
        *(float4*)&Qs[q * 36 + d4] = v;
    }
    __syncthreads();
    uint32_t qa[2][4][4];
    #pragma unroll
    for (int qt = 0; qt < 2; ++qt)
        #pragma unroll
        for (int kk = 0; kk < 4; ++kk) {
            const int r1 = (qb + qt * 16 + g) * 36 + kk * 8 + t;
            const int r2 = r1 + 8 * 36;
            qa[qt][kk][0] = __float_as_uint(Qs[r1]);
            qa[qt][kk][1] = __float_as_uint(Qs[r2]);
            qa[qt][kk][2] = __float_as_uint(Qs[r1 + 4]);
            qa[qt][kk][3] = __float_as_uint(Qs[r2 + 4]);
        }

    float rsum[4] = {};
    float oacc[2][4][4] = {};

    const int srcA = (lane & 28) | (t >> 1);
    const int srcB = srcA | 2;
    const bool odd = (t & 1);

    for (int mc = ks * 8; mc < ks * 8 + 8; ++mc) {
        const int m0 = mc * 64;
        __syncthreads();
        #pragma unroll
        for (int i = 0; i < 4; ++i) {
            const int m = (tid >> 3) + i * 16;
            const int d4 = (tid & 7) * 4;
            *(float4*)&Ks[m * 36 + d4] =
                *(const float4*)&qkTb[(size_t)(m0 + m) * 512 + 256 + h * 32 + d4];
            const int d = (tid >> 4) + i * 8;
            const int m4 = (tid & 15) * 4;
            *(float4*)&Vs[d * 68 + m4] = *(const float4*)&vp[(size_t)d * 1024 + m0 + m4];
        }
        __syncthreads();

        #pragma unroll
        for (int nt = 0; nt < 8; ++nt) {
            float sf0[4] = {}, sf1[4] = {};
            #pragma unroll
            for (int kk = 0; kk < 4; ++kk) {
                const int bb = (nt * 8 + g) * 36 + kk * 8 + t;
                uint32_t bf[2];
                bf[0] = __float_as_uint(Ks[bb]); bf[1] = __float_as_uint(Ks[bb + 4]);
                mma8(sf0, qa[0][kk], bf);
                mma8(sf1, qa[1][kk], bf);
            }
            const float p00 = exp2f(sf0[0]), p01 = exp2f(sf0[1]);
            const float p02 = exp2f(sf0[2]), p03 = exp2f(sf0[3]);
            const float p10 = exp2f(sf1[0]), p11 = exp2f(sf1[1]);
            const float p12 = exp2f(sf1[2]), p13 = exp2f(sf1[3]);
            rsum[0] += p00 + p01; rsum[1] += p02 + p03;
            rsum[2] += p10 + p11; rsum[3] += p12 + p13;

            uint32_t pa0[4], pa1[4];
            {
                float e, o;
                e = __shfl_sync(0xffffffffu, p00, srcA);
                o = __shfl_sync(0xffffffffu, p01, srcA);
                pa0[0] = f2tf(odd ? o : e);
                e = __shfl_sync(0xffffffffu, p02, srcA);
                o = __shfl_sync(0xffffffffu, p03, srcA);
                pa0[1] = f2tf(odd ? o : e);
                e = __shfl_sync(0xffffffffu, p00, srcB);
                o = __shfl_sync(0xffffffffu, p01, srcB);
                pa0[2] = f2tf(odd ? o : e);
                e = __shfl_sync(0xffffffffu, p02, srcB);
                o = __shfl_sync(0xffffffffu, p03, srcB);
                pa0[3] = f2tf(odd ? o : e);

                e = __shfl_sync(0xffffffffu, p10, srcA);
                o = __shfl_sync(0xffffffffu, p11, srcA);
                pa1[0] = f2tf(odd ? o : e);
                e = __shfl_sync(0xffffffffu, p12, srcA);
                o = __shfl_sync(0xffffffffu, p13, srcA);
                pa1[1] = f2tf(odd ? o : e);
                e = __shfl_sync(0xffffffffu, p10, srcB);
                o = __shfl_sync(0xffffffffu, p11, srcB);
                pa1[2] = f2tf(odd ? o : e);
                e = __shfl_sync(0xffffffffu, p12, srcB);
                o = __shfl_sync(0xffffffffu, p13, srcB);
                pa1[3] = f2tf(odd ? o : e);
            }

            #pragma unroll
            for (int dt = 0; dt < 4; ++dt) {
                const int vb = (dt * 8 + g) * 68 + nt * 8 + t;
                uint32_t bf[2];
                bf[0] = __float_as_uint(Vs[vb]); bf[1] = __float_as_uint(Vs[vb + 4]);
                mma8(oacc[0][dt], pa0, bf);
                mma8(oacc[1][dt], pa1, bf);
            }
        }
    }

    #pragma unroll
    for (int j = 0; j < 4; ++j) {
        rsum[j] += __shfl_xor_sync(0xffffffffu, rsum[j], 1);
        rsum[j] += __shfl_xor_sync(0xffffffffu, rsum[j], 2);
    }
    if (t == 0) {
        float* rp = g_rs + ((size_t)ks * 64 + bh) * 1024 + q0 + qb;
        rp[g] = rsum[0]; rp[8 + g] = rsum[1];
        rp[16 + g] = rsum[2]; rp[24 + g] = rsum[3];
    }

    #pragma unroll
    for (int dt = 0; dt < 4; ++dt) {
        const int cc = dt * 8 + 2 * t;
        *(float2*)&Qs[(qb +  0 + g) * 36 + cc] = make_float2(oacc[0][dt][0], oacc[0][dt][1]);
        *(float2*)&Qs[(qb +  8 + g) * 36 + cc] = make_float2(oacc[0][dt][2], oacc[0][dt][3]);
        *(float2*)&Qs[(qb + 16 + g) * 36 + cc] = make_float2(oacc[1][dt][0], oacc[1][dt][1]);
        *(float2*)&Qs[(qb + 24 + g) * 36 + cc] = make_float2(oacc[1][dt][2], oacc[1][dt][3]);
    }
    __syncthreads();
    float* pout = g_part + (size_t)ks * 8 * 1024 * 256;
    #pragma unroll
    for (int i = 0; i < 8; ++i) {
        const int flat = i * 128 + tid;
        const int q = flat >> 3, d4 = (flat & 7) * 4;
        *(float4*)&pout[((size_t)b * 1024 + q0 + q) * 256 + h * 32 + d4] =
            *(const float4*)&Qs[q * 36 + d4];
    }
}

// ---------------------------------------------------------------------------
// LePE + split-K merge: attT[b][n][c] = tf(conv(v)+bias + (p0+p1)*inv).
// 32-ch group == one head (cg == h), so inv is one scalar pair per column.
// Bandwidth-idle conv kernel absorbs the streamed merge.
// ---------------------------------------------------------------------------
__global__ __launch_bounds__(128) void lepe_merge_kernel(const float* __restrict__ lw,
                                                         const float* __restrict__ lb)
{
    __shared__ float sv[32 * 289];
    __shared__ float wch[800];
    __shared__ float bch[32];

    const int cg = blockIdx.x;       // 0..7 == head
    const int rb = blockIdx.y;       // 0..7 (4-row band)
    const int b  = blockIdx.z;
    const int tid = threadIdx.x;

    for (int i = tid; i < 800; i += 128) wch[i] = lw[cg * 32 * 25 + i];
    if (tid < 32) bch[tid] = lb[cg * 32 + tid];
    for (int i = tid; i < 32 * 8 * 4; i += 128) {
        const int c = i >> 5, rsd = (i >> 2) & 7, e = i & 3;
        const int col = (e < 2) ? e : 32 + e;
        sv[c * 289 + rsd * 36 + col] = 0.0f;
    }
    const float* vbase = g_v + ((size_t)b * 256 + cg * 32) * 1024;
    for (int i = tid; i < 2048; i += 128) {
        const int c = i >> 6, rsd = (i >> 3) & 7, q4 = (i & 7) * 4;
        const int gr = rb * 4 - 2 + rsd;
        float4 v = make_float4(0.f, 0.f, 0.f, 0.f);
        if ((unsigned)gr < 32u)
            v = *(const float4*)&vbase[(size_t)c * 1024 + gr * 32 + q4];
        float* p = &sv[c * 289 + rsd * 36 + 2 + q4];
        p[0] = v.x; p[1] = v.y; p[2] = v.z; p[3] = v.w;
    }
    __syncthreads();

    const int c = tid & 31, r = tid >> 5;
    const float* svc = &sv[c * 289];
    const float* wc = &wch[c * 25];
    const float bias = bch[c];

    const size_t nbase = (size_t)b * 1024 + (rb * 4 + r) * 32;   // + col
    float* op        = g_attT + nbase * 256 + cg * 32 + c;
    const float* q0p = g_part + nbase * 256 + cg * 32 + c;
    const float* q1p = q0p + (size_t)8 * 1024 * 256;
    const float* r0p = g_rs + ((size_t)b * 8 + cg) * 1024 + (rb * 4 + r) * 32;
    const float* r1p = r0p + (size_t)64 * 1024;

    #pragma unroll 4
    for (int col = 0; col < 32; ++col) {
        float acc = bias;
        #pragma unroll
        for (int kh = 0; kh < 5; ++kh)
            #pragma unroll
            for (int kw = 0; kw < 5; ++kw)
                acc += wc[kh * 5 + kw] * svc[(r + kh) * 36 + col + kw];
        const float inv = 1.0f / (r0p[col] + r1p[col]);
        const float po = q0p[(size_t)col * 256] + q1p[(size_t)col * 256];
        op[(size_t)col * 256] = tf(acc + po * inv);
    }
}

// ---------------------------------------------------------------------------
// Proj GEMM (r7-measured form): out = W @ (attT)^T + bias.
// Single B stream, register-prefetch double buffer, cvt in storereg.
// ---------------------------------------------------------------------------
__global__ __launch_bounds__(128) void gemm_proj(const float* __restrict__ W,
                                                 const float* __restrict__ Bt,
                                                 float* __restrict__ C,
                                                 const float* __restrict__ bias)
{
    __shared__ float sm[4608];
    float* As = sm;          // 64 x 36  [m][k]
    float* Bs = sm + 2304;   // 64 x 36  [n][k]

    const int tid = threadIdx.x;
    const int bm = blockIdx.y * 64, bn = blockIdx.x * 64, b = blockIdx.z;
    const float* Btb = Bt + (size_t)b * 1024 * 256;
    float* Cb = C + (size_t)b * 256 * 1024;

    const int lane = tid & 31, wrp = tid >> 5;
    const int g = lane >> 2, t = lane & 3;
    const int qb = wrp * 16;

    const int lm = (tid >> 3);
    const int lk = (tid & 7) * 4;

    float4 pa[4], pb[4];
    auto loadreg = [&](int kc) {
        const int k0 = kc * 32;
        #pragma unroll
        for (int i = 0; i < 4; ++i) {
            pa[i] = *(const float4*)&W[(size_t)(bm + lm + i * 16) * 256 + k0 + lk];
            pb[i] = *(const float4*)&Btb[(size_t)(bn + lm + i * 16) * 256 + k0 + lk];
        }
    };
    auto storereg = [&]() {
        #pragma unroll
        for (int i = 0; i < 4; ++i) {
            const int m = lm + i * 16;
            float4 a = pa[i], bvv = pb[i];
            a.x = tf(a.x); a.y = tf(a.y); a.z = tf(a.z); a.w = tf(a.w);
            bvv.x = tf(bvv.x); bvv.y = tf(bvv.y); bvv.z = tf(bvv.z); bvv.w = tf(bvv.w);
            *(float4*)&As[m * 36 + lk] = a;
            *(float4*)&Bs[m * 36 + lk] = bvv;
        }
    };

    float cf[8][4] = {};

    loadreg(0); storereg(); __syncthreads();
    for (int kc = 0; kc < 8; ++kc) {
        if (kc < 7) loadreg(kc + 1);

        #pragma unroll
        for (int kk = 0; kk < 4; ++kk) {
            const int r1 = (qb + g) * 36 + kk * 8 + t;
            const int r2 = r1 + 8 * 36;
            uint32_t a[4];
            a[0] = __float_as_uint(As[r1]);     a[1] = __float_as_uint(As[r2]);
            a[2] = __float_as_uint(As[r1 + 4]); a[3] = __float_as_uint(As[r2 + 4]);
            #pragma unroll
            for (int nt = 0; nt < 8; ++nt) {
                const int bb = (nt * 8 + g) * 36 + kk * 8 + t;
                uint32_t bf[2];
                bf[0] = __float_as_uint(Bs[bb]); bf[1] = __float_as_uint(Bs[bb + 4]);
                mma8(cf[nt], a, bf);
            }
        }
        __syncthreads();
        if (kc < 7) { storereg(); __syncthreads(); }
    }

    float* Cs = sm;   // 64 x 68
    const int row1 = qb + g, row2 = row1 + 8;
    const float bi1 = bias[bm + row1];
    const float bi2 = bias[bm + row2];
    #pragma unroll
    for (int nt = 0; nt < 8; ++nt) {
        *(float2*)&Cs[row1 * 68 + nt * 8 + 2 * t] = make_float2(cf[nt][0] + bi1, cf[nt][1] + bi1);
        *(float2*)&Cs[row2 * 68 + nt * 8 + 2 * t] = make_float2(cf[nt][2] + bi2, cf[nt][3] + bi2);
    }
    __syncthreads();
    #pragma unroll
    for (int i = 0; i < 8; ++i) {
        const int flat = i * 128 + tid;
        const int m = flat >> 4, n4 = (flat & 15) * 4;
        *(float4*)&Cb[(size_t)(bm + m) * 1024 + bn + n4] = *(const float4*)&Cs[m * 68 + n4];
    }
}

// ---------------------------------------------------------------------------
extern "C" void kernel_launch(void* const* d_in, const int* in_sizes, int n_in,
                              void* d_out, int out_size)
{
    const float* x      = (const float*)d_in[0];
    const float* qkv_w  = (const float*)d_in[1];
    const float* proj_w = (const float*)d_in[2];
    const float* proj_b = (const float*)d_in[3];
    const float* lepe_w = (const float*)d_in[4];
    const float* lepe_b = (const float*)d_in[5];
    float* out = (float*)d_out;

    float* attT_p;
    cudaGetSymbolAddress((void**)&attT_p, g_attT);

    // 1) qkv = qkv_w @ x -> q,k transposed (g_qkT), v (g_v), tf32-rounded
    gemm_qkv<<<dim3(16, 12, 8), 128>>>(qkv_w, x);
    // 2) attention split-K x2 -> unnormalized partials + row sums (1024 blocks)
    attn_kernel<<<dim3(16, 64), 128>>>();
    // 3) LePE + merge: attT = tf(conv(v)+bias + (p0+p1)/rs)
    lepe_merge_kernel<<<dim3(8, 8, 8), 128>>>(lepe_w, lepe_b);
    // 4) out = proj_w @ attT^T + proj_b
    gemm_proj<<<dim3(16, 4, 8), 128>>>(proj_w, attT_p, out, proj_b);
}

// round 16
// speedup vs baseline: 1.0882x; 1.0882x over previous
#include <cuda_runtime.h>
#include <cstdint>
#include <cstddef>

#define SCALE 0.17677669529663687f            // 32^-0.5
#define S2LOG (SCALE * 1.4426950408889634f)   // SCALE * log2(e)

// ---------------- scratch (allocation-free rule) ----------------
static __device__ float g_wr  [(size_t)768 * 256];        // qkv_w tf32-rounded
static __device__ float g_wp  [(size_t)256 * 256];        // proj_w tf32-rounded
static __device__ float g_qkT [(size_t)8 * 1024 * 512];   // q,k transposed [b][n][512] (tf32)
static __device__ float g_v   [(size_t)8 * 256 * 1024];   // v [b][c][n] (tf32)
static __device__ float g_attT[(size_t)8 * 1024 * 256];   // attn out [b][n][c] (fp32)
static __device__ float g_lepe[(size_t)8 * 1024 * 256];   // lepe out [b][n][c] (fp32)

// ---------------- helpers ----------------
__device__ __forceinline__ uint32_t f2tf(float x) {
    uint32_t r; asm("cvt.rna.tf32.f32 %0, %1;" : "=r"(r) : "f"(x)); return r;
}
__device__ __forceinline__ float tf(float x) { return __uint_as_float(f2tf(x)); }

__device__ __forceinline__ void mma8(float* d, const uint32_t* a, const uint32_t* b) {
    asm volatile(
        "mma.sync.aligned.m16n8k8.row.col.f32.tf32.tf32.f32 "
        "{%0,%1,%2,%3}, {%4,%5,%6,%7}, {%8,%9}, {%0,%1,%2,%3};"
        : "+f"(d[0]), "+f"(d[1]), "+f"(d[2]), "+f"(d[3])
        : "r"(a[0]), "r"(a[1]), "r"(a[2]), "r"(a[3]), "r"(b[0]), "r"(b[1]));
}

// ---------------------------------------------------------------------------
__global__ __launch_bounds__(256) void round_copy(const float4* __restrict__ in,
                                                  float4* __restrict__ out, int n4)
{
    int i = blockIdx.x * 256 + threadIdx.x;
    if (i < n4) {
        float4 v = in[i];
        v.x = tf(v.x); v.y = tf(v.y); v.z = tf(v.z); v.w = tf(v.w);
        out[i] = v;
    }
}

// ---------------------------------------------------------------------------
// QKV GEMM (r13 structure; W pre-rounded -> no A-side cvt):
// qkv[m][n] = sum_k W[m][k]*x[b][k][n]
// ---------------------------------------------------------------------------
__global__ __launch_bounds__(128) void gemm_qkv(const float* __restrict__ W,
                                                const float* __restrict__ X)
{
    __shared__ float sm[4608];
    float* As = sm;          // 64 x 36  [m][k]
    float* Bs = sm + 2304;   // 32 x 72  [k][n]

    const int tid = threadIdx.x;
    const int bm = blockIdx.y * 64, bn = blockIdx.x * 64, b = blockIdx.z;
    const float* Xb = X + (size_t)b * 256 * 1024;

    const int lane = tid & 31, wrp = tid >> 5;
    const int g = lane >> 2, t = lane & 3;
    const int qb = wrp * 16;

    float cf[8][4] = {};

    for (int kc = 0; kc < 8; ++kc) {
        const int k0 = kc * 32;
        if (kc) __syncthreads();
        #pragma unroll
        for (int i = 0; i < 4; ++i) {
            const int m = (tid >> 3) + i * 16;
            const int kq = (tid & 7) * 4;
            *(float4*)&As[m * 36 + kq] =
                *(const float4*)&W[(size_t)(bm + m) * 256 + k0 + kq];   // pre-rounded
            const int k = (tid >> 4) + i * 8;
            const int n4 = (tid & 15) * 4;
            float4 bv = *(const float4*)&Xb[(size_t)(k0 + k) * 1024 + bn + n4];
            bv.x = tf(bv.x); bv.y = tf(bv.y); bv.z = tf(bv.z); bv.w = tf(bv.w);
            *(float4*)&Bs[k * 72 + n4] = bv;
        }
        __syncthreads();

        #pragma unroll
        for (int kk = 0; kk < 4; ++kk) {
            const int r1 = (qb + g) * 36 + kk * 8 + t;
            const int r2 = r1 + 8 * 36;
            uint32_t a[4];
            a[0] = __float_as_uint(As[r1]);     a[1] = __float_as_uint(As[r2]);
            a[2] = __float_as_uint(As[r1 + 4]); a[3] = __float_as_uint(As[r2 + 4]);
            #pragma unroll
            for (int nt = 0; nt < 8; ++nt) {
                uint32_t bb[2];
                bb[0] = __float_as_uint(Bs[(kk * 8 + t) * 72 + nt * 8 + g]);
                bb[1] = __float_as_uint(Bs[(kk * 8 + t + 4) * 72 + nt * 8 + g]);
                mma8(cf[nt], a, bb);
            }
        }
    }
    __syncthreads();

    if (bm < 512) {
        float* CsT = sm;    // 64 x 68, [n][m]
        #pragma unroll
        for (int nt = 0; nt < 8; ++nt) {
            const int n0 = nt * 8 + 2 * t;
            CsT[(n0 + 0) * 68 + qb + g]     = tf(cf[nt][0]);
            CsT[(n0 + 1) * 68 + qb + g]     = tf(cf[nt][1]);
            CsT[(n0 + 0) * 68 + qb + g + 8] = tf(cf[nt][2]);
            CsT[(n0 + 1) * 68 + qb + g + 8] = tf(cf[nt][3]);
        }
        __syncthreads();
        #pragma unroll
        for (int i = 0; i < 8; ++i) {
            const int flat = i * 128 + tid;
            const int n = flat >> 4, m4 = (flat & 15) * 4;
            *(float4*)&g_qkT[((size_t)b * 1024 + bn + n) * 512 + bm + m4] =
                *(const float4*)&CsT[n * 68 + m4];
        }
    } else {
        float* Cs = sm;     // 64 x 68
        const int row1 = qb + g, row2 = row1 + 8;
        #pragma unroll
        for (int nt = 0; nt < 8; ++nt) {
            *(float2*)&Cs[row1 * 68 + nt * 8 + 2 * t] = make_float2(tf(cf[nt][0]), tf(cf[nt][1]));
            *(float2*)&Cs[row2 * 68 + nt * 8 + 2 * t] = make_float2(tf(cf[nt][2]), tf(cf[nt][3]));
        }
        __syncthreads();
        #pragma unroll
        for (int i = 0; i < 8; ++i) {
            const int flat = i * 128 + tid;
            const int m = flat >> 4, n4 = (flat & 15) * 4;
            *(float4*)&g_v[((size_t)b * 256 + bm - 512 + m) * 1024 + bn + n4] =
                *(const float4*)&Cs[m * 68 + n4];
        }
    }
}

// ---------------------------------------------------------------------------
// Attention (r13 winner, verbatim): block = 128 queries of one (b,h),
// 4 warps x 32q each, plain-exp softmax, fp32 out.
// ---------------------------------------------------------------------------
__global__ __launch_bounds__(128, 4) void attn_kernel()
{
    __shared__ float Ks[64 * 36];    // [m][d]
    __shared__ float Vs[32 * 68];    // [d][m]
    __shared__ float Ps[128 * 68];   // Q staging / P / O staging

    const int tid = threadIdx.x;
    const int bh = blockIdx.y;
    const int b = bh >> 3, h = bh & 7;
    const int q0 = blockIdx.x * 128;

    const float* qkTb = g_qkT + (size_t)b * 1024 * 512;
    const float* vp   = g_v   + ((size_t)b * 256 + h * 32) * 1024;

    const int lane = tid & 31, wrp = tid >> 5;
    const int g = lane >> 2, t = lane & 3;
    const int qb = wrp * 32;

    #pragma unroll
    for (int i = 0; i < 8; ++i) {
        const int q = (tid >> 3) + i * 16;
        const int d4 = (tid & 7) * 4;
        float4 v = *(const float4*)&qkTb[(size_t)(q0 + q) * 512 + h * 32 + d4];
        v.x = tf(v.x * S2LOG); v.y = tf(v.y * S2LOG);
        v.z = tf(v.z * S2LOG); v.w = tf(v.w * S2LOG);
        *(float4*)&Ps[q * 68 + d4] = v;
    }
    __syncthreads();
    uint32_t qa[2][4][4];
    #pragma unroll
    for (int qt = 0; qt < 2; ++qt)
        #pragma unroll
        for (int kk = 0; kk < 4; ++kk) {
            const int r1 = (qb + qt * 16 + g) * 68 + kk * 8 + t;
            const int r2 = r1 + 8 * 68;
            qa[qt][kk][0] = __float_as_uint(Ps[r1]);
            qa[qt][kk][1] = __float_as_uint(Ps[r2]);
            qa[qt][kk][2] = __float_as_uint(Ps[r1 + 4]);
            qa[qt][kk][3] = __float_as_uint(Ps[r2 + 4]);
        }

    float rs[4] = {};
    float oacc[2][4][4] = {};

    for (int mc = 0; mc < 16; ++mc) {
        const int m0 = mc * 64;
        __syncthreads();
        #pragma unroll
        for (int i = 0; i < 4; ++i) {
            const int m = (tid >> 3) + i * 16;
            const int d4 = (tid & 7) * 4;
            *(float4*)&Ks[m * 36 + d4] =
                *(const float4*)&qkTb[(size_t)(m0 + m) * 512 + 256 + h * 32 + d4];
            const int d = (tid >> 4) + i * 8;
            const int m4 = (tid & 15) * 4;
            *(float4*)&Vs[d * 68 + m4] = *(const float4*)&vp[(size_t)d * 1024 + m0 + m4];
        }
        __syncthreads();

        #pragma unroll
        for (int nt = 0; nt < 8; ++nt) {
            float sf0[4] = {}, sf1[4] = {};
            #pragma unroll
            for (int kk = 0; kk < 4; ++kk) {
                const int bb = (nt * 8 + g) * 36 + kk * 8 + t;
                uint32_t bf[2];
                bf[0] = __float_as_uint(Ks[bb]); bf[1] = __float_as_uint(Ks[bb + 4]);
                mma8(sf0, qa[0][kk], bf);
                mma8(sf1, qa[1][kk], bf);
            }
            const float p00 = exp2f(sf0[0]), p01 = exp2f(sf0[1]);
            const float p02 = exp2f(sf0[2]), p03 = exp2f(sf0[3]);
            const float p10 = exp2f(sf1[0]), p11 = exp2f(sf1[1]);
            const float p12 = exp2f(sf1[2]), p13 = exp2f(sf1[3]);
            rs[0] += p00 + p01; rs[1] += p02 + p03;
            rs[2] += p10 + p11; rs[3] += p12 + p13;
            const int cc = nt * 8 + 2 * t;
            *(float2*)&Ps[(qb +  0 + g) * 68 + cc] = make_float2(tf(p00), tf(p01));
            *(float2*)&Ps[(qb +  8 + g) * 68 + cc] = make_float2(tf(p02), tf(p03));
            *(float2*)&Ps[(qb + 16 + g) * 68 + cc] = make_float2(tf(p10), tf(p11));
            *(float2*)&Ps[(qb + 24 + g) * 68 + cc] = make_float2(tf(p12), tf(p13));
        }
        __syncwarp();

        #pragma unroll
        for (int kk = 0; kk < 8; ++kk) {
            const int r1 = (qb + g) * 68 + kk * 8 + t;
            uint32_t pa0[4], pa1[4];
            pa0[0] = __float_as_uint(Ps[r1]);
            pa0[1] = __float_as_uint(Ps[r1 + 8 * 68]);
            pa0[2] = __float_as_uint(Ps[r1 + 4]);
            pa0[3] = __float_as_uint(Ps[r1 + 8 * 68 + 4]);
            pa1[0] = __float_as_uint(Ps[r1 + 16 * 68]);
            pa1[1] = __float_as_uint(Ps[r1 + 24 * 68]);
            pa1[2] = __float_as_uint(Ps[r1 + 16 * 68 + 4]);
            pa1[3] = __float_as_uint(Ps[r1 + 24 * 68 + 4]);
            #pragma unroll
            for (int nt = 0; nt < 4; ++nt) {
                const int vb = (nt * 8 + g) * 68 + kk * 8 + t;
                uint32_t bf[2];
                bf[0] = __float_as_uint(Vs[vb]); bf[1] = __float_as_uint(Vs[vb + 4]);
                mma8(oacc[0][nt], pa0, bf);
                mma8(oacc[1][nt], pa1, bf);
            }
        }
        __syncwarp();
    }

    #pragma unroll
    for (int j = 0; j < 4; ++j) {
        rs[j] += __shfl_xor_sync(0xffffffffu, rs[j], 1);
        rs[j] += __shfl_xor_sync(0xffffffffu, rs[j], 2);
    }
    const float inv0 = 1.0f / rs[0], inv1 = 1.0f / rs[1];
    const float inv2 = 1.0f / rs[2], inv3 = 1.0f / rs[3];

    #pragma unroll
    for (int nt = 0; nt < 4; ++nt) {
        const int cc = nt * 8 + 2 * t;
        *(float2*)&Ps[(qb +  0 + g) * 68 + cc] =
            make_float2(oacc[0][nt][0] * inv0, oacc[0][nt][1] * inv0);
        *(float2*)&Ps[(qb +  8 + g) * 68 + cc] =
            make_float2(oacc[0][nt][2] * inv1, oacc[0][nt][3] * inv1);
        *(float2*)&Ps[(qb + 16 + g) * 68 + cc] =
            make_float2(oacc[1][nt][0] * inv2, oacc[1][nt][1] * inv2);
        *(float2*)&Ps[(qb + 24 + g) * 68 + cc] =
            make_float2(oacc[1][nt][2] * inv3, oacc[1][nt][3] * inv3);
    }
    __syncthreads();
    #pragma unroll
    for (int i = 0; i < 8; ++i) {
        const int flat = i * 128 + tid;
        const int q = flat >> 3, d4 = (flat & 7) * 4;
        *(float4*)&g_attT[((size_t)b * 1024 + q0 + q) * 256 + h * 32 + d4] =
            *(const float4*)&Ps[q * 68 + d4];
    }
}

// ---------------------------------------------------------------------------
// LePE (r13 winner, verbatim): g_lepe = dwconv5x5(v) + lepe_b, write-only.
// ---------------------------------------------------------------------------
__global__ __launch_bounds__(128) void lepe_kernel(const float* __restrict__ lw,
                                                   const float* __restrict__ lb)
{
    __shared__ float sv[32 * 289];
    __shared__ float wch[800];
    __shared__ float bch[32];

    const int cg = blockIdx.x, rb = blockIdx.y, b = blockIdx.z;
    const int tid = threadIdx.x;

    for (int i = tid; i < 800; i += 128) wch[i] = lw[cg * 32 * 25 + i];
    if (tid < 32) bch[tid] = lb[cg * 32 + tid];
    for (int i = tid; i < 32 * 8 * 4; i += 128) {
        const int c = i >> 5, rsd = (i >> 2) & 7, e = i & 3;
        const int col = (e < 2) ? e : 32 + e;
        sv[c * 289 + rsd * 36 + col] = 0.0f;
    }
    const float* vbase = g_v + ((size_t)b * 256 + cg * 32) * 1024;
    for (int i = tid; i < 2048; i += 128) {
        const int c = i >> 6, rsd = (i >> 3) & 7, q4 = (i & 7) * 4;
        const int gr = rb * 4 - 2 + rsd;
        float4 v = make_float4(0.f, 0.f, 0.f, 0.f);
        if ((unsigned)gr < 32u)
            v = *(const float4*)&vbase[(size_t)c * 1024 + gr * 32 + q4];
        float* p = &sv[c * 289 + rsd * 36 + 2 + q4];
        p[0] = v.x; p[1] = v.y; p[2] = v.z; p[3] = v.w;
    }
    __syncthreads();

    const int c = tid & 31, r = tid >> 5;
    const float* svc = &sv[c * 289];
    const float* wc = &wch[c * 25];
    const float bias = bch[c];
    float* op = g_lepe + ((size_t)b * 1024 + (rb * 4 + r) * 32) * 256 + cg * 32 + c;
    #pragma unroll 4
    for (int col = 0; col < 32; ++col) {
        float acc = bias;
        #pragma unroll
        for (int kh = 0; kh < 5; ++kh)
            #pragma unroll
            for (int kw = 0; kw < 5; ++kw)
                acc += wc[kh * 5 + kw] * svc[(r + kh) * 36 + col + kw];
        op[(size_t)col * 256] = acc;
    }
}

// ---------------------------------------------------------------------------
// Proj GEMM (r13 winner; W pre-rounded -> no A-side cvt):
// out = W @ (attT + lepe)^T + bias, register-prefetch double buffer.
// ---------------------------------------------------------------------------
__global__ __launch_bounds__(128) void gemm_proj(const float* __restrict__ W,
                                                 const float* __restrict__ At,
                                                 const float* __restrict__ Lt,
                                                 float* __restrict__ C,
                                                 const float* __restrict__ bias)
{
    __shared__ float sm[4608];
    float* As = sm;          // 64 x 36  [m][k]
    float* Bs = sm + 2304;   // 64 x 36  [n][k]

    const int tid = threadIdx.x;
    const int bm = blockIdx.y * 64, bn = blockIdx.x * 64, b = blockIdx.z;
    const float* Atb = At + (size_t)b * 1024 * 256;
    const float* Ltb = Lt + (size_t)b * 1024 * 256;
    float* Cb = C + (size_t)b * 256 * 1024;

    const int lane = tid & 31, wrp = tid >> 5;
    const int g = lane >> 2, t = lane & 3;
    const int qb = wrp * 16;

    const int lm = (tid >> 3);
    const int lk = (tid & 7) * 4;

    float4 pa[4], pb[4], pl[4];
    auto loadreg = [&](int kc) {
        const int k0 = kc * 32;
        #pragma unroll
        for (int i = 0; i < 4; ++i) {
            pa[i] = *(const float4*)&W[(size_t)(bm + lm + i * 16) * 256 + k0 + lk];
            pb[i] = *(const float4*)&Atb[(size_t)(bn + lm + i * 16) * 256 + k0 + lk];
            pl[i] = *(const float4*)&Ltb[(size_t)(bn + lm + i * 16) * 256 + k0 + lk];
        }
    };
    auto storereg = [&]() {
        #pragma unroll
        for (int i = 0; i < 4; ++i) {
            const int m = lm + i * 16;
            float4 bv;
            bv.x = tf(pb[i].x + pl[i].x); bv.y = tf(pb[i].y + pl[i].y);
            bv.z = tf(pb[i].z + pl[i].z); bv.w = tf(pb[i].w + pl[i].w);
            *(float4*)&As[m * 36 + lk] = pa[i];     // pre-rounded
            *(float4*)&Bs[m * 36 + lk] = bv;
        }
    };

    float cf[8][4] = {};

    loadreg(0); storereg(); __syncthreads();
    for (int kc = 0; kc < 8; ++kc) {
        if (kc < 7) loadreg(kc + 1);

        #pragma unroll
        for (int kk = 0; kk < 4; ++kk) {
            const int r1 = (qb + g) * 36 + kk * 8 + t;
            const int r2 = r1 + 8 * 36;
            uint32_t a[4];
            a[0] = __float_as_uint(As[r1]);     a[1] = __float_as_uint(As[r2]);
            a[2] = __float_as_uint(As[r1 + 4]); a[3] = __float_as_uint(As[r2 + 4]);
            #pragma unroll
            for (int nt = 0; nt < 8; ++nt) {
                const int bb = (nt * 8 + g) * 36 + kk * 8 + t;
                uint32_t bf[2];
                bf[0] = __float_as_uint(Bs[bb]); bf[1] = __float_as_uint(Bs[bb + 4]);
                mma8(cf[nt], a, bf);
            }
        }
        __syncthreads();
        if (kc < 7) { storereg(); __syncthreads(); }
    }

    float* Cs = sm;   // 64 x 68
    const int row1 = qb + g, row2 = row1 + 8;
    const float bi1 = bias[bm + row1];
    const float bi2 = bias[bm + row2];
    #pragma unroll
    for (int nt = 0; nt < 8; ++nt) {
        *(float2*)&Cs[row1 * 68 + nt * 8 + 2 * t] = make_float2(cf[nt][0] + bi1, cf[nt][1] + bi1);
        *(float2*)&Cs[row2 * 68 + nt * 8 + 2 * t] = make_float2(cf[nt][2] + bi2, cf[nt][3] + bi2);
    }
    __syncthreads();
    #pragma unroll
    for (int i = 0; i < 8; ++i) {
        const int flat = i * 128 + tid;
        const int m = flat >> 4, n4 = (flat & 15) * 4;
        *(float4*)&Cb[(size_t)(bm + m) * 1024 + bn + n4] = *(const float4*)&Cs[m * 68 + n4];
    }
}

// ---------------------------------------------------------------------------
extern "C" void kernel_launch(void* const* d_in, const int* in_sizes, int n_in,
                              void* d_out, int out_size)
{
    const float* x      = (const float*)d_in[0];
    const float* qkv_w  = (const float*)d_in[1];
    const float* proj_w = (const float*)d_in[2];
    const float* proj_b = (const float*)d_in[3];
    const float* lepe_w = (const float*)d_in[4];
    const float* lepe_b = (const float*)d_in[5];
    float* out = (float*)d_out;

    float *wr_p, *wp_p, *attT_p, *lepe_p;
    cudaGetSymbolAddress((void**)&wr_p, g_wr);
    cudaGetSymbolAddress((void**)&wp_p, g_wp);
    cudaGetSymbolAddress((void**)&attT_p, g_attT);
    cudaGetSymbolAddress((void**)&lepe_p, g_lepe);

    // 0) pre-round weights to tf32 (removes per-tile cvt in both GEMMs)
    round_copy<<<192, 256>>>((const float4*)qkv_w, (float4*)wr_p, 49152);
    round_copy<<<64, 256>>>((const float4*)proj_w, (float4*)wp_p, 16384);
    // 1) qkv = wr @ x -> q,k transposed (g_qkT), v (g_v), tf32-rounded
    gemm_qkv<<<dim3(16, 12, 8), 128>>>(wr_p, x);
    // 2) LePE (write-only, independent): g_lepe = conv(v)+bias
    lepe_kernel<<<dim3(8, 8, 8), 128>>>(lepe_w, lepe_b);
    // 3) attention -> attT (fp32)
    attn_kernel<<<dim3(8, 64), 128>>>();
    // 4) out = wp @ (attT + lepe) + proj_b
    gemm_proj<<<dim3(16, 4, 8), 128>>>(wp_p, attT_p, lepe_p, out, proj_b);
}

// round 17
// speedup vs baseline: 1.1328x; 1.0410x over previous
#include <cuda_runtime.h>
#include <cstdint>
#include <cstddef>

#define SCALE 0.17677669529663687f            // 32^-0.5
#define S2LOG (SCALE * 1.4426950408889634f)   // SCALE * log2(e)

// ---------------- scratch (allocation-free rule) ----------------
static __device__ float g_qkT [(size_t)8 * 1024 * 512];   // q,k transposed [b][n][512] (tf32)
static __device__ float g_v   [(size_t)8 * 256 * 1024];   // v [b][c][n] (tf32)
static __device__ float g_attT[(size_t)8 * 1024 * 256];   // attn out [b][n][c] (fp32)
static __device__ float g_lepe[(size_t)8 * 1024 * 256];   // lepe out [b][n][c] (fp32)

// ---------------- helpers ----------------
__device__ __forceinline__ uint32_t f2tf(float x) {
    uint32_t r; asm("cvt.rna.tf32.f32 %0, %1;" : "=r"(r) : "f"(x)); return r;
}
__device__ __forceinline__ float tf(float x) { return __uint_as_float(f2tf(x)); }

__device__ __forceinline__ void mma8(float* d, const uint32_t* a, const uint32_t* b) {
    asm volatile(
        "mma.sync.aligned.m16n8k8.row.col.f32.tf32.tf32.f32 "
        "{%0,%1,%2,%3}, {%4,%5,%6,%7}, {%8,%9}, {%0,%1,%2,%3};"
        : "+f"(d[0]), "+f"(d[1]), "+f"(d[2]), "+f"(d[3])
        : "r"(a[0]), "r"(a[1]), "r"(a[2]), "r"(a[3]), "r"(b[0]), "r"(b[1]));
}

// ---------------------------------------------------------------------------
// QKV GEMM (137.6-winner, verbatim): qkv[m][n] = sum_k W[m][k]*x[b][k][n]
// ---------------------------------------------------------------------------
__global__ __launch_bounds__(128) void gemm_qkv(const float* __restrict__ W,
                                                const float* __restrict__ X)
{
    __shared__ float sm[4608];
    float* As = sm;          // 64 x 36  [m][k]
    float* Bs = sm + 2304;   // 32 x 72  [k][n]

    const int tid = threadIdx.x;
    const int bm = blockIdx.y * 64, bn = blockIdx.x * 64, b = blockIdx.z;
    const float* Xb = X + (size_t)b * 256 * 1024;

    const int lane = tid & 31, wrp = tid >> 5;
    const int g = lane >> 2, t = lane & 3;
    const int qb = wrp * 16;

    float cf[8][4] = {};

    for (int kc = 0; kc < 8; ++kc) {
        const int k0 = kc * 32;
        if (kc) __syncthreads();
        #pragma unroll
        for (int i = 0; i < 4; ++i) {
            const int m = (tid >> 3) + i * 16;
            const int kq = (tid & 7) * 4;
            float4 av = *(const float4*)&W[(size_t)(bm + m) * 256 + k0 + kq];
            av.x = tf(av.x); av.y = tf(av.y); av.z = tf(av.z); av.w = tf(av.w);
            *(float4*)&As[m * 36 + kq] = av;
            const int k = (tid >> 4) + i * 8;
            const int n4 = (tid & 15) * 4;
            float4 bv = *(const float4*)&Xb[(size_t)(k0 + k) * 1024 + bn + n4];
            bv.x = tf(bv.x); bv.y = tf(bv.y); bv.z = tf(bv.z); bv.w = tf(bv.w);
            *(float4*)&Bs[k * 72 + n4] = bv;
        }
        __syncthreads();

        #pragma unroll
        for (int kk = 0; kk < 4; ++kk) {
            const int r1 = (qb + g) * 36 + kk * 8 + t;
            const int r2 = r1 + 8 * 36;
            uint32_t a[4];
            a[0] = __float_as_uint(As[r1]);     a[1] = __float_as_uint(As[r2]);
            a[2] = __float_as_uint(As[r1 + 4]); a[3] = __float_as_uint(As[r2 + 4]);
            #pragma unroll
            for (int nt = 0; nt < 8; ++nt) {
                uint32_t bb[2];
                bb[0] = __float_as_uint(Bs[(kk * 8 + t) * 72 + nt * 8 + g]);
                bb[1] = __float_as_uint(Bs[(kk * 8 + t + 4) * 72 + nt * 8 + g]);
                mma8(cf[nt], a, bb);
            }
        }
    }
    __syncthreads();

    if (bm < 512) {
        float* CsT = sm;    // 64 x 68, [n][m]
        #pragma unroll
        for (int nt = 0; nt < 8; ++nt) {
            const int n0 = nt * 8 + 2 * t;
            CsT[(n0 + 0) * 68 + qb + g]     = tf(cf[nt][0]);
            CsT[(n0 + 1) * 68 + qb + g]     = tf(cf[nt][1]);
            CsT[(n0 + 0) * 68 + qb + g + 8] = tf(cf[nt][2]);
            CsT[(n0 + 1) * 68 + qb + g + 8] = tf(cf[nt][3]);
        }
        __syncthreads();
        #pragma unroll
        for (int i = 0; i < 8; ++i) {
            const int flat = i * 128 + tid;
            const int n = flat >> 4, m4 = (flat & 15) * 4;
            *(float4*)&g_qkT[((size_t)b * 1024 + bn + n) * 512 + bm + m4] =
                *(const float4*)&CsT[n * 68 + m4];
        }
    } else {
        float* Cs = sm;     // 64 x 68
        const int row1 = qb + g, row2 = row1 + 8;
        #pragma unroll
        for (int nt = 0; nt < 8; ++nt) {
            *(float2*)&Cs[row1 * 68 + nt * 8 + 2 * t] = make_float2(tf(cf[nt][0]), tf(cf[nt][1]));
            *(float2*)&Cs[row2 * 68 + nt * 8 + 2 * t] = make_float2(tf(cf[nt][2]), tf(cf[nt][3]));
        }
        __syncthreads();
        #pragma unroll
        for (int i = 0; i < 8; ++i) {
            const int flat = i * 128 + tid;
            const int m = flat >> 4, n4 = (flat & 15) * 4;
            *(float4*)&g_v[((size_t)b * 256 + bm - 512 + m) * 1024 + bn + n4] =
                *(const float4*)&Cs[m * 68 + n4];
        }
    }
}

// ---------------------------------------------------------------------------
// Attention (137.6-winner, verbatim): block = 128 queries of one (b,h),
// 4 warps x 32q each, plain-exp softmax, fp32 out.
// ---------------------------------------------------------------------------
__global__ __launch_bounds__(128, 4) void attn_kernel()
{
    __shared__ float Ks[64 * 36];    // [m][d]
    __shared__ float Vs[32 * 68];    // [d][m]
    __shared__ float Ps[128 * 68];   // Q staging / P / O staging

    const int tid = threadIdx.x;
    const int bh = blockIdx.y;
    const int b = bh >> 3, h = bh & 7;
    const int q0 = blockIdx.x * 128;

    const float* qkTb = g_qkT + (size_t)b * 1024 * 512;
    const float* vp   = g_v   + ((size_t)b * 256 + h * 32) * 1024;

    const int lane = tid & 31, wrp = tid >> 5;
    const int g = lane >> 2, t = lane & 3;
    const int qb = wrp * 32;

    #pragma unroll
    for (int i = 0; i < 8; ++i) {
        const int q = (tid >> 3) + i * 16;
        const int d4 = (tid & 7) * 4;
        float4 v = *(const float4*)&qkTb[(size_t)(q0 + q) * 512 + h * 32 + d4];
        v.x = tf(v.x * S2LOG); v.y = tf(v.y * S2LOG);
        v.z = tf(v.z * S2LOG); v.w = tf(v.w * S2LOG);
        *(float4*)&Ps[q * 68 + d4] = v;
    }
    __syncthreads();
    uint32_t qa[2][4][4];
    #pragma unroll
    for (int qt = 0; qt < 2; ++qt)
        #pragma unroll
        for (int kk = 0; kk < 4; ++kk) {
            const int r1 = (qb + qt * 16 + g) * 68 + kk * 8 + t;
            const int r2 = r1 + 8 * 68;
            qa[qt][kk][0] = __float_as_uint(Ps[r1]);
            qa[qt][kk][1] = __float_as_uint(Ps[r2]);
            qa[qt][kk][2] = __float_as_uint(Ps[r1 + 4]);
            qa[qt][kk][3] = __float_as_uint(Ps[r2 + 4]);
        }

    float rs[4] = {};
    float oacc[2][4][4] = {};

    for (int mc = 0; mc < 16; ++mc) {
        const int m0 = mc * 64;
        __syncthreads();
        #pragma unroll
        for (int i = 0; i < 4; ++i) {
            const int m = (tid >> 3) + i * 16;
            const int d4 = (tid & 7) * 4;
            *(float4*)&Ks[m * 36 + d4] =
                *(const float4*)&qkTb[(size_t)(m0 + m) * 512 + 256 + h * 32 + d4];
            const int d = (tid >> 4) + i * 8;
            const int m4 = (tid & 15) * 4;
            *(float4*)&Vs[d * 68 + m4] = *(const float4*)&vp[(size_t)d * 1024 + m0 + m4];
        }
        __syncthreads();

        #pragma unroll
        for (int nt = 0; nt < 8; ++nt) {
            float sf0[4] = {}, sf1[4] = {};
            #pragma unroll
            for (int kk = 0; kk < 4; ++kk) {
                const int bb = (nt * 8 + g) * 36 + kk * 8 + t;
                uint32_t bf[2];
                bf[0] = __float_as_uint(Ks[bb]); bf[1] = __float_as_uint(Ks[bb + 4]);
                mma8(sf0, qa[0][kk], bf);
                mma8(sf1, qa[1][kk], bf);
            }
            const float p00 = exp2f(sf0[0]), p01 = exp2f(sf0[1]);
            const float p02 = exp2f(sf0[2]), p03 = exp2f(sf0[3]);
            const float p10 = exp2f(sf1[0]), p11 = exp2f(sf1[1]);
            const float p12 = exp2f(sf1[2]), p13 = exp2f(sf1[3]);
            rs[0] += p00 + p01; rs[1] += p02 + p03;
            rs[2] += p10 + p11; rs[3] += p12 + p13;
            const int cc = nt * 8 + 2 * t;
            *(float2*)&Ps[(qb +  0 + g) * 68 + cc] = make_float2(tf(p00), tf(p01));
            *(float2*)&Ps[(qb +  8 + g) * 68 + cc] = make_float2(tf(p02), tf(p03));
            *(float2*)&Ps[(qb + 16 + g) * 68 + cc] = make_float2(tf(p10), tf(p11));
            *(float2*)&Ps[(qb + 24 + g) * 68 + cc] = make_float2(tf(p12), tf(p13));
        }
        __syncwarp();

        #pragma unroll
        for (int kk = 0; kk < 8; ++kk) {
            const int r1 = (qb + g) * 68 + kk * 8 + t;
            uint32_t pa0[4], pa1[4];
            pa0[0] = __float_as_uint(Ps[r1]);
            pa0[1] = __float_as_uint(Ps[r1 + 8 * 68]);
            pa0[2] = __float_as_uint(Ps[r1 + 4]);
            pa0[3] = __float_as_uint(Ps[r1 + 8 * 68 + 4]);
            pa1[0] = __float_as_uint(Ps[r1 + 16 * 68]);
            pa1[1] = __float_as_uint(Ps[r1 + 24 * 68]);
            pa1[2] = __float_as_uint(Ps[r1 + 16 * 68 + 4]);
            pa1[3] = __float_as_uint(Ps[r1 + 24 * 68 + 4]);
            #pragma unroll
            for (int nt = 0; nt < 4; ++nt) {
                const int vb = (nt * 8 + g) * 68 + kk * 8 + t;
                uint32_t bf[2];
                bf[0] = __float_as_uint(Vs[vb]); bf[1] = __float_as_uint(Vs[vb + 4]);
                mma8(oacc[0][nt], pa0, bf);
                mma8(oacc[1][nt], pa1, bf);
            }
        }
        __syncwarp();
    }

    #pragma unroll
    for (int j = 0; j < 4; ++j) {
        rs[j] += __shfl_xor_sync(0xffffffffu, rs[j], 1);
        rs[j] += __shfl_xor_sync(0xffffffffu, rs[j], 2);
    }
    const float inv0 = 1.0f / rs[0], inv1 = 1.0f / rs[1];
    const float inv2 = 1.0f / rs[2], inv3 = 1.0f / rs[3];

    #pragma unroll
    for (int nt = 0; nt < 4; ++nt) {
        const int cc = nt * 8 + 2 * t;
        *(float2*)&Ps[(qb +  0 + g) * 68 + cc] =
            make_float2(oacc[0][nt][0] * inv0, oacc[0][nt][1] * inv0);
        *(float2*)&Ps[(qb +  8 + g) * 68 + cc] =
            make_float2(oacc[0][nt][2] * inv1, oacc[0][nt][3] * inv1);
        *(float2*)&Ps[(qb + 16 + g) * 68 + cc] =
            make_float2(oacc[1][nt][0] * inv2, oacc[1][nt][1] * inv2);
        *(float2*)&Ps[(qb + 24 + g) * 68 + cc] =
            make_float2(oacc[1][nt][2] * inv3, oacc[1][nt][3] * inv3);
    }
    __syncthreads();
    #pragma unroll
    for (int i = 0; i < 8; ++i) {
        const int flat = i * 128 + tid;
        const int q = flat >> 3, d4 = (flat & 7) * 4;
        *(float4*)&g_attT[((size_t)b * 1024 + q0 + q) * 256 + h * 32 + d4] =
            *(const float4*)&Ps[q * 68 + d4];
    }
}

// ---------------------------------------------------------------------------
// LePE (write-only): g_lepe = dwconv5x5(v) + lepe_b.
// 256 threads: 32 ch x 4 rows x 2 column-halves -> 16 cols/thread
// (halves the serial conv chain, doubles warps/SM vs the 128-thr version).
// ---------------------------------------------------------------------------
__global__ __launch_bounds__(256) void lepe_kernel(const float* __restrict__ lw,
                                                   const float* __restrict__ lb)
{
    __shared__ float sv[32 * 289];   // 32 ch x (8 rows x 36 cols, padded)
    __shared__ float wch[800];       // 32 x 25
    __shared__ float bch[32];

    const int cg = blockIdx.x;       // 0..7 (32-channel group)
    const int rb = blockIdx.y;       // 0..7 (4-row band)
    const int b  = blockIdx.z;
    const int tid = threadIdx.x;     // 0..255

    for (int i = tid; i < 800; i += 256) wch[i] = lw[cg * 32 * 25 + i];
    if (tid < 32) bch[tid] = lb[cg * 32 + tid];
    // zero pad columns (0,1,34,35) for all 8 smem rows
    for (int i = tid; i < 32 * 8 * 4; i += 256) {
        const int c = i >> 5, rsd = (i >> 2) & 7, e = i & 3;
        const int col = (e < 2) ? e : 32 + e;
        sv[c * 289 + rsd * 36 + col] = 0.0f;
    }
    // load v rows [rb*4-2, rb*4+6) for 32 channels (2048 float4)
    const float* vbase = g_v + ((size_t)b * 256 + cg * 32) * 1024;
    for (int i = tid; i < 2048; i += 256) {
        const int c = i >> 6, rsd = (i >> 3) & 7, q4 = (i & 7) * 4;
        const int gr = rb * 4 - 2 + rsd;
        float4 v = make_float4(0.f, 0.f, 0.f, 0.f);
        if ((unsigned)gr < 32u)
            v = *(const float4*)&vbase[(size_t)c * 1024 + gr * 32 + q4];
        float* p = &sv[c * 289 + rsd * 36 + 2 + q4];
        p[0] = v.x; p[1] = v.y; p[2] = v.z; p[3] = v.w;
    }
    __syncthreads();

    const int c = tid & 31;              // channel
    const int r = (tid >> 5) & 3;        // row within band
    const int half = tid >> 7;           // column half (0/1)
    const float* svc = &sv[c * 289];
    const float* wc = &wch[c * 25];
    const float bias = bch[c];
    float* op = g_lepe + ((size_t)b * 1024 + (rb * 4 + r) * 32) * 256 + cg * 32 + c;
    const int c0 = half * 16;
    #pragma unroll 4
    for (int col = c0; col < c0 + 16; ++col) {
        float acc = bias;
        #pragma unroll
        for (int kh = 0; kh < 5; ++kh)
            #pragma unroll
            for (int kw = 0; kw < 5; ++kw)
                acc += wc[kh * 5 + kw] * svc[(r + kh) * 36 + col + kw];
        op[(size_t)col * 256] = acc;
    }
}

// ---------------------------------------------------------------------------
// Proj GEMM (137.6-winner, verbatim): out = W @ (attT + lepe)^T + bias.
// Register-prefetch double buffer; B = tf(attT + lepe).
// ---------------------------------------------------------------------------
__global__ __launch_bounds__(128) void gemm_proj(const float* __restrict__ W,
                                                 const float* __restrict__ At,
                                                 const float* __restrict__ Lt,
                                                 float* __restrict__ C,
                                                 const float* __restrict__ bias)
{
    __shared__ float sm[4608];
    float* As = sm;          // 64 x 36  [m][k]
    float* Bs = sm + 2304;   // 64 x 36  [n][k]

    const int tid = threadIdx.x;
    const int bm = blockIdx.y * 64, bn = blockIdx.x * 64, b = blockIdx.z;
    const float* Atb = At + (size_t)b * 1024 * 256;
    const float* Ltb = Lt + (size_t)b * 1024 * 256;
    float* Cb = C + (size_t)b * 256 * 1024;

    const int lane = tid & 31, wrp = tid >> 5;
    const int g = lane >> 2, t = lane & 3;
    const int qb = wrp * 16;

    const int lm = (tid >> 3);
    const int lk = (tid & 7) * 4;

    float4 pa[4], pb[4], pl[4];
    auto loadreg = [&](int kc) {
        const int k0 = kc * 32;
        #pragma unroll
        for (int i = 0; i < 4; ++i) {
            pa[i] = *(const float4*)&W[(size_t)(bm + lm + i * 16) * 256 + k0 + lk];
            pb[i] = *(const float4*)&Atb[(size_t)(bn + lm + i * 16) * 256 + k0 + lk];
            pl[i] = *(const float4*)&Ltb[(size_t)(bn + lm + i * 16) * 256 + k0 + lk];
        }
    };
    auto storereg = [&]() {
        #pragma unroll
        for (int i = 0; i < 4; ++i) {
            const int m = lm + i * 16;
            float4 a = pa[i];
            a.x = tf(a.x); a.y = tf(a.y); a.z = tf(a.z); a.w = tf(a.w);
            float4 bv;
            bv.x = tf(pb[i].x + pl[i].x); bv.y = tf(pb[i].y + pl[i].y);
            bv.z = tf(pb[i].z + pl[i].z); bv.w = tf(pb[i].w + pl[i].w);
            *(float4*)&As[m * 36 + lk] = a;
            *(float4*)&Bs[m * 36 + lk] = bv;
        }
    };

    float cf[8][4] = {};

    loadreg(0); storereg(); __syncthreads();
    for (int kc = 0; kc < 8; ++kc) {
        if (kc < 7) loadreg(kc + 1);

        #pragma unroll
        for (int kk = 0; kk < 4; ++kk) {
            const int r1 = (qb + g) * 36 + kk * 8 + t;
            const int r2 = r1 + 8 * 36;
            uint32_t a[4];
            a[0] = __float_as_uint(As[r1]);     a[1] = __float_as_uint(As[r2]);
            a[2] = __float_as_uint(As[r1 + 4]); a[3] = __float_as_uint(As[r2 + 4]);
            #pragma unroll
            for (int nt = 0; nt < 8; ++nt) {
                const int bb = (nt * 8 + g) * 36 + kk * 8 + t;
                uint32_t bf[2];
                bf[0] = __float_as_uint(Bs[bb]); bf[1] = __float_as_uint(Bs[bb + 4]);
                mma8(cf[nt], a, bf);
            }
        }
        __syncthreads();
        if (kc < 7) { storereg(); __syncthreads(); }
    }

    float* Cs = sm;   // 64 x 68
    const int row1 = qb + g, row2 = row1 + 8;
    const float bi1 = bias[bm + row1];
    const float bi2 = bias[bm + row2];
    #pragma unroll
    for (int nt = 0; nt < 8; ++nt) {
        *(float2*)&Cs[row1 * 68 + nt * 8 + 2 * t] = make_float2(cf[nt][0] + bi1, cf[nt][1] + bi1);
        *(float2*)&Cs[row2 * 68 + nt * 8 + 2 * t] = make_float2(cf[nt][2] + bi2, cf[nt][3] + bi2);
    }
    __syncthreads();
    #pragma unroll
    for (int i = 0; i < 8; ++i) {
        const int flat = i * 128 + tid;
        const int m = flat >> 4, n4 = (flat & 15) * 4;
        *(float4*)&Cb[(size_t)(bm + m) * 1024 + bn + n4] = *(const float4*)&Cs[m * 68 + n4];
    }
}

// ---------------------------------------------------------------------------
extern "C" void kernel_launch(void* const* d_in, const int* in_sizes, int n_in,
                              void* d_out, int out_size)
{
    const float* x      = (const float*)d_in[0];
    const float* qkv_w  = (const float*)d_in[1];
    const float* proj_w = (const float*)d_in[2];
    const float* proj_b = (const float*)d_in[3];
    const float* lepe_w = (const float*)d_in[4];
    const float* lepe_b = (const float*)d_in[5];
    float* out = (float*)d_out;

    float *attT_p, *lepe_p;
    cudaGetSymbolAddress((void**)&attT_p, g_attT);
    cudaGetSymbolAddress((void**)&lepe_p, g_lepe);

    // 1) qkv = qkv_w @ x -> q,k transposed (g_qkT), v (g_v), tf32-rounded
    gemm_qkv<<<dim3(16, 12, 8), 128>>>(qkv_w, x);
    // 2) LePE (write-only, 256 threads): g_lepe = conv(v)+bias
    lepe_kernel<<<dim3(8, 8, 8), 256>>>(lepe_w, lepe_b);
    // 3) attention -> attT (fp32)
    attn_kernel<<<dim3(8, 64), 128>>>();
    // 4) out = proj_w @ (attT + lepe) + proj_b
    gemm_proj<<<dim3(16, 4, 8), 128>>>(proj_w, attT_p, lepe_p, out, proj_b);
}